// round 7
// baseline (speedup 1.0000x reference)
#include <cuda_runtime.h>
#include <cuda_bf16.h>
#include <cstdint>

// Problem constants (fixed by the reference)
#define NB 32      // batch
#define NZ 4000    // nodes
#define NIN 32     // in features
#define NH 64      // hidden
#define NE 64000   // edges

#define NY  (NB * NZ * NIN / 4)   // 1,024,000 float4 loads of x
#define NYB (NY / 256)            // 4000 ydot blocks
#define NEB ((NE + 255) / 256)    // 250 histogram blocks

// Scratch (device globals; zero-initialized at module load; k_out re-zeroes
// g_acc / g_deg after use so every kernel_launch execution starts clean).
__device__ __align__(16) float g_y[NZ * NB];    // y[z*NB + b] = x[b,z,:] . v
__device__ __align__(16) float g_acc[NZ * NB];  // accumulator, [z][b]
__device__ int g_deg[NZ];                       // in-degree EXCLUDING self-loop

// ---------------------------------------------------------------------------
// K1: fused ydot + degree histogram.
// Blocks [0, NYB): per-block compute v = W@fc_W into smem (8 FMA/thread +
//   8-lane shuffle reduce; W is L1-resident after first touch), then thread t
//   loads float4 #t of x (flat, perfectly coalesced); lanes 8k..8k+7 cover one
//   (b,z) row; 3-step xor-shuffle reduce; leader writes y[z*NB+b].
// Blocks [NYB, NYB+NEB): degree histogram over edge destinations
//   (g_deg starts at 0: zero-init on first call, reset by k_out afterwards).
// ---------------------------------------------------------------------------
__global__ void k_ydot_hist(const float* __restrict__ x,
                            const int* __restrict__ dst,
                            const float* __restrict__ W,
                            const float* __restrict__ fcW) {
    if (blockIdx.x < NYB) {
        __shared__ __align__(16) float sv[NIN];
        const int tx = threadIdx.x;
        {   // v[i] = sum_h W[i*NH+h] * fcW[h]; thread (i = tx>>3, j = tx&7)
            int i = tx >> 3;
            int j = tx & 7;
            float p = 0.f;
            #pragma unroll
            for (int k = 0; k < 8; ++k)
                p += W[i * NH + j * 8 + k] * fcW[j * 8 + k];
            p += __shfl_xor_sync(0xFFFFFFFFu, p, 1);
            p += __shfl_xor_sync(0xFFFFFFFFu, p, 2);
            p += __shfl_xor_sync(0xFFFFFFFFu, p, 4);
            if (j == 0) sv[i] = p;
        }
        __syncthreads();

        int t = blockIdx.x * 256 + tx;                   // < NY
        float4 xv = __ldcs(&reinterpret_cast<const float4*>(x)[t]);
        float4 vv = reinterpret_cast<const float4*>(sv)[tx & 7];
        float p = xv.x * vv.x + xv.y * vv.y + xv.z * vv.z + xv.w * vv.w;
        p += __shfl_xor_sync(0xFFFFFFFFu, p, 1);
        p += __shfl_xor_sync(0xFFFFFFFFu, p, 2);
        p += __shfl_xor_sync(0xFFFFFFFFu, p, 4);
        if ((tx & 7) == 0) {
            int f = t >> 3;             // row index = b*NZ + z
            int b = f / NZ;
            int z = f - b * NZ;
            g_y[z * NB + b] = p;
        }
    } else {
        int e = (blockIdx.x - NYB) * 256 + threadIdx.x;
        if (e < NE) atomicAdd(&g_deg[__ldg(&dst[e])], 1);
    }
}

// ---------------------------------------------------------------------------
// K2: edge scatter with VECTOR atomics. 8 threads per edge, each covers a
// float4 of the 32 batches: 512K float4 REDs instead of 2.05M scalar REDs
// (the LTS atomic unit is op-throughput bound, not byte bound).
// acc4[d*8+q] += norm * y4[s*8+q],  norm = rsqrt((deg_s+1)(deg_d+1)).
// g_acc starts at 0 (zero-init / reset by k_out).
// ---------------------------------------------------------------------------
__global__ void k_scatter(const int* __restrict__ src,
                          const int* __restrict__ dst) {
    int t = blockIdx.x * blockDim.x + threadIdx.x;   // t = e*8 + q
    int e = t >> 3;
    int q = t & 7;
    if (e >= NE) return;
    int s = __ldg(&src[e]);
    int d = __ldg(&dst[e]);
    float norm = rsqrtf((float)((g_deg[s] + 1) * (g_deg[d] + 1)));
    float4 y4 = reinterpret_cast<const float4*>(g_y)[s * 8 + q];
    float4 m = make_float4(norm * y4.x, norm * y4.y, norm * y4.z, norm * y4.w);
    atomicAdd(&reinterpret_cast<float4*>(g_acc)[d * 8 + q], m);
}

// ---------------------------------------------------------------------------
// K3: out[b][z] = acc[z][b] + y[z][b]/(deg+1) + const, via 32x32 smem tile.
// Warp 0 recomputes const = bias.fc_W + fc_b. After the tile read, this block
// RESETS its slice of g_acc and g_deg to zero for the next graph replay.
// ---------------------------------------------------------------------------
__global__ void k_out(const float* __restrict__ bias,
                      const float* __restrict__ fcW,
                      const float* __restrict__ fcb,
                      float* __restrict__ out) {
    __shared__ float tile[32][33];
    __shared__ float sconst;
    int tx = threadIdx.x, ty = threadIdx.y;

    if (ty == 0) {   // const = bias . fcW + fcb (warp reduce)
        float p = bias[tx * 2] * fcW[tx * 2] + bias[tx * 2 + 1] * fcW[tx * 2 + 1];
        #pragma unroll
        for (int o = 16; o > 0; o >>= 1)
            p += __shfl_xor_sync(0xFFFFFFFFu, p, o);
        if (tx == 0) sconst = p + fcb[0];
    }

    int zb = blockIdx.x * 32;                 // NZ % 32 == 0 (4000 = 125*32)
    int z = zb + ty;
    float invdeg = 1.0f / (float)(g_deg[z] + 1);   // broadcast within warp
    int idx = z * NB + tx;
    tile[ty][tx] = g_acc[idx] + g_y[idx] * invdeg;
    __syncthreads();

    g_acc[idx] = 0.f;                         // self-clean for next replay
    if (ty == 2) g_deg[zb + tx] = 0;          // all deg reads happened pre-sync

    out[(size_t)ty * NZ + zb + tx] = tile[tx][ty] + sconst;
}

// ---------------------------------------------------------------------------
extern "C" void kernel_launch(void* const* d_in, const int* in_sizes, int n_in,
                              void* d_out, int out_size) {
    const float* x    = (const float*)d_in[0];   // [32,4000,32]
    const int*   ei   = (const int*)  d_in[1];   // [2,64000]
    const float* W    = (const float*)d_in[2];   // [32,64]
    const float* bias = (const float*)d_in[3];   // [64]
    const float* fcW  = (const float*)d_in[4];   // [64]
    const float* fcb  = (const float*)d_in[5];   // [1]
    float* out = (float*)d_out;                  // [32,4000]

    const int* src = ei;
    const int* dst = ei + NE;

    k_ydot_hist<<<NYB + NEB, 256>>>(x, dst, W, fcW);
    k_scatter<<<(NE * 8) / 256, 256>>>(src, dst);
    k_out<<<NZ / 32, dim3(32, 32)>>>(bias, fcW, fcb, out);
}

// round 8
// speedup vs baseline: 1.2137x; 1.2137x over previous
#include <cuda_runtime.h>
#include <cuda_bf16.h>
#include <cstdint>

// Problem constants (fixed by the reference)
#define NB 32      // batch
#define NZ 4000    // nodes
#define NIN 32     // in features
#define NH 64      // hidden
#define NE 64000   // edges

#define NY  (NB * NZ * NIN / 4)   // 1,024,000 float4 loads of x
#define NYB (NY / 256)            // 4000 main blocks
#define EPB (NE / NYB)            // 16 histogram edges per block

// Scratch (device globals; zero-initialized at module load; k_out re-zeroes
// g_acc / g_deg / g_flag after use so every execution starts clean).
__device__ __align__(16) float g_y[NZ * NB];    // y[z*NB + b] = x[b,z,:] . v
__device__ __align__(16) float g_acc[NZ * NB];  // accumulator, [z][b]
__device__ int g_deg[NZ];                       // in-degree EXCLUDING self-loop
__device__ __align__(16) float g_v[NIN];        // W @ fc_W (computed by block 0)
__device__ float g_const;                       // b . fc_W + fc_b
__device__ unsigned g_flag;                     // v/const ready flag

// ---------------------------------------------------------------------------
// K1: fused (v,const once) + degree histogram + ydot.
//  - every block: histogram for its 16-edge slice (independent of v)
//  - block 0: v[i] = sum_h W[i,h]*fcW[h]; const = bias.fcW + fcb; fence; flag=1
//  - blocks != 0: spin on flag (bounded by block 0's ~1us compute)
//  - all blocks: coalesced ydot; thread t loads float4 #t of x; lanes 8k..8k+7
//    cover one (b,z) row; 3-step xor-shuffle reduce; leader writes y[z*NB+b].
// ---------------------------------------------------------------------------
__global__ void k_main(const float* __restrict__ x,
                       const int* __restrict__ dst,
                       const float* __restrict__ W,
                       const float* __restrict__ bias,
                       const float* __restrict__ fcW,
                       const float* __restrict__ fcb) {
    const int tx = threadIdx.x;
    const int bid = blockIdx.x;

    // (a) histogram slice (before the spin so it overlaps block 0's work)
    if (tx < EPB) {
        int e = bid * EPB + tx;
        atomicAdd(&g_deg[__ldg(&dst[e])], 1);
    }

    // (b) produce / wait for v and const
    if (bid == 0) {
        if (tx < NIN * 8) {   // v: thread (i = tx>>3, j = tx&7), 8-lane reduce
            int i = tx >> 3;
            int j = tx & 7;
            float p = 0.f;
            #pragma unroll
            for (int k = 0; k < 8; ++k)
                p += W[i * NH + j * 8 + k] * fcW[j * 8 + k];
            p += __shfl_xor_sync(0xFFFFFFFFu, p, 1);
            p += __shfl_xor_sync(0xFFFFFFFFu, p, 2);
            p += __shfl_xor_sync(0xFFFFFFFFu, p, 4);
            if (j == 0) g_v[i] = p;
        }
        __threadfence();
        __syncthreads();
        if (tx == 0) {
            float s = fcb[0];
            #pragma unroll
            for (int h = 0; h < NH; ++h) s += bias[h] * fcW[h];
            g_const = s;
            __threadfence();
            atomicExch(&g_flag, 1u);
        }
    } else {
        if (tx == 0) {
            while (atomicAdd(&g_flag, 0u) == 0u) { }
        }
        __syncthreads();
    }

    // (c) ydot (g_v is final: ordered via flag acquire pattern above)
    int t = bid * 256 + tx;                          // < NY
    float4 xv = __ldcs(&reinterpret_cast<const float4*>(x)[t]);
    float4 vv = reinterpret_cast<const float4*>(g_v)[tx & 7];
    float p = xv.x * vv.x + xv.y * vv.y + xv.z * vv.z + xv.w * vv.w;
    p += __shfl_xor_sync(0xFFFFFFFFu, p, 1);
    p += __shfl_xor_sync(0xFFFFFFFFu, p, 2);
    p += __shfl_xor_sync(0xFFFFFFFFu, p, 4);
    if ((tx & 7) == 0) {
        int f = t >> 3;             // row index = b*NZ + z
        int b = f / NZ;
        int z = f - b * NZ;
        g_y[z * NB + b] = p;
    }
}

// ---------------------------------------------------------------------------
// K2: edge scatter with VECTOR atomics. 8 threads per edge, each covers a
// float4 of the 32 batches: 512K float4 REDs instead of 2.05M scalar REDs.
// acc4[d*8+q] += norm * y4[s*8+q],  norm = rsqrt((deg_s+1)(deg_d+1)).
// ---------------------------------------------------------------------------
__global__ void k_scatter(const int* __restrict__ src,
                          const int* __restrict__ dst) {
    int t = blockIdx.x * blockDim.x + threadIdx.x;   // t = e*8 + q
    int e = t >> 3;
    int q = t & 7;
    if (e >= NE) return;
    int s = __ldg(&src[e]);
    int d = __ldg(&dst[e]);
    float norm = rsqrtf((float)((g_deg[s] + 1) * (g_deg[d] + 1)));
    float4 y4 = reinterpret_cast<const float4*>(g_y)[s * 8 + q];
    float4 m = make_float4(norm * y4.x, norm * y4.y, norm * y4.z, norm * y4.w);
    atomicAdd(&reinterpret_cast<float4*>(g_acc)[d * 8 + q], m);
}

// ---------------------------------------------------------------------------
// K3: out[b][z] = acc[z][b] + y[z][b]/(deg+1) + const, via 32x32 smem tile.
// After the tile read this block RESETS its slice of g_acc / g_deg (and
// block 0 resets g_flag) so the next graph replay starts from clean state.
// ---------------------------------------------------------------------------
__global__ void k_out(float* __restrict__ out) {
    __shared__ float tile[32][33];
    int tx = threadIdx.x, ty = threadIdx.y;

    int zb = blockIdx.x * 32;                 // NZ % 32 == 0 (4000 = 125*32)
    int z = zb + ty;
    float invdeg = 1.0f / (float)(g_deg[z] + 1);   // broadcast within warp
    int idx = z * NB + tx;
    tile[ty][tx] = g_acc[idx] + g_y[idx] * invdeg;
    __syncthreads();

    g_acc[idx] = 0.f;                         // self-clean for next replay
    if (ty == 2) g_deg[zb + tx] = 0;          // deg reads all happened pre-sync
    if (blockIdx.x == 0 && ty == 3 && tx == 0) g_flag = 0u;

    out[(size_t)ty * NZ + zb + tx] = tile[tx][ty] + g_const;
}

// ---------------------------------------------------------------------------
extern "C" void kernel_launch(void* const* d_in, const int* in_sizes, int n_in,
                              void* d_out, int out_size) {
    const float* x    = (const float*)d_in[0];   // [32,4000,32]
    const int*   ei   = (const int*)  d_in[1];   // [2,64000]
    const float* W    = (const float*)d_in[2];   // [32,64]
    const float* bias = (const float*)d_in[3];   // [64]
    const float* fcW  = (const float*)d_in[4];   // [64]
    const float* fcb  = (const float*)d_in[5];   // [1]
    float* out = (float*)d_out;                  // [32,4000]

    const int* src = ei;
    const int* dst = ei + NE;

    k_main<<<NYB, 256>>>(x, dst, W, bias, fcW, fcb);
    k_scatter<<<(NE * 8) / 256, 256>>>(src, dst);
    k_out<<<NZ / 32, dim3(32, 32)>>>(out);
}

// round 9
// speedup vs baseline: 1.5435x; 1.2718x over previous
#include <cuda_runtime.h>
#include <cuda_bf16.h>
#include <cstdint>

// Problem constants (fixed by the reference)
#define NB 32      // batch
#define NZ 4000    // nodes
#define NIN 32     // in features
#define NH 64      // hidden
#define NE 64000   // edges

#define NY  (NB * NZ * NIN / 4)   // 1,024,000 float4 loads of x
#define NYB (NY / 256)            // 4000 ydot blocks
#define NEB (NE / 256)            // 250 histogram blocks

// Scratch (device globals; zero-initialized at module load; k_out re-zeroes
// g_acc / g_deg after use so every execution starts clean).
__device__ __align__(16) float g_w[NZ * NB];    // w[z*NB+b] = dinv_z * (x[b,z,:].v)
__device__ __align__(16) float g_acc[NZ * NB];  // acc[z][b] = sum_{s->z} w[s][b]
__device__ int g_deg[NZ];                       // in-degree EXCLUDING self-loop
__device__ __align__(16) float g_v[NIN];        // W @ fc_W
__device__ float g_const;                       // bias . fc_W + fc_b

// ---------------------------------------------------------------------------
// K1: degree histogram (blocks 0..NEB-1) + v/const (block NEB).
// g_deg starts at 0 (zero-init on first call, reset by k_out afterwards).
// ---------------------------------------------------------------------------
__global__ void k_hist_v(const int* __restrict__ dst,
                         const float* __restrict__ W,
                         const float* __restrict__ bias,
                         const float* __restrict__ fcW,
                         const float* __restrict__ fcb) {
    const int tx = threadIdx.x;
    if (blockIdx.x < NEB) {
        int e = blockIdx.x * 256 + tx;
        atomicAdd(&g_deg[__ldg(&dst[e])], 1);
    } else {
        // v[i] = sum_h W[i*NH+h]*fcW[h]; thread (i = tx>>3, j = tx&7)
        int i = tx >> 3;
        int j = tx & 7;
        float p = 0.f;
        #pragma unroll
        for (int k = 0; k < 8; ++k)
            p += W[i * NH + j * 8 + k] * fcW[j * 8 + k];
        p += __shfl_xor_sync(0xFFFFFFFFu, p, 1);
        p += __shfl_xor_sync(0xFFFFFFFFu, p, 2);
        p += __shfl_xor_sync(0xFFFFFFFFu, p, 4);
        if (j == 0) g_v[i] = p;
        if (tx == 0) {
            float s = fcb[0];
            #pragma unroll
            for (int h = 0; h < NH; ++h) s += bias[h] * fcW[h];
            g_const = s;
        }
    }
}

// ---------------------------------------------------------------------------
// K2: streaming ydot. Thread t loads float4 #t of x (flat, coalesced);
// lanes 8k..8k+7 cover one (b,z) row; 3-step xor-shuffle reduce; leader
// applies dinv_z = rsqrt(deg[z]+1) (deg is final) and stores w = dinv_z * y.
// ---------------------------------------------------------------------------
__global__ void k_ydot(const float* __restrict__ x) {
    int t = blockIdx.x * 256 + threadIdx.x;              // < NY
    float4 xv = __ldcs(&reinterpret_cast<const float4*>(x)[t]);
    float4 vv = reinterpret_cast<const float4*>(g_v)[threadIdx.x & 7];
    float p = xv.x * vv.x + xv.y * vv.y + xv.z * vv.z + xv.w * vv.w;
    p += __shfl_xor_sync(0xFFFFFFFFu, p, 1);
    p += __shfl_xor_sync(0xFFFFFFFFu, p, 2);
    p += __shfl_xor_sync(0xFFFFFFFFu, p, 4);
    if ((t & 7) == 0) {
        int f = t >> 3;             // row index = b*NZ + z
        int b = f / NZ;
        int z = f - b * NZ;
        float dinv = rsqrtf((float)(g_deg[z] + 1));
        g_w[z * NB + b] = p * dinv;
    }
}

// ---------------------------------------------------------------------------
// K3: minimal edge scatter: acc4[d*8+q] += w4[s*8+q]. 8 threads per edge,
// float4 REDs (512K ops). No deg loads, no rsqrt, no multiplies.
// g_acc starts at 0 (zero-init / reset by k_out).
// ---------------------------------------------------------------------------
__global__ void k_scatter(const int* __restrict__ src,
                          const int* __restrict__ dst) {
    int t = blockIdx.x * blockDim.x + threadIdx.x;   // t = e*8 + q
    int e = t >> 3;
    int q = t & 7;
    if (e >= NE) return;
    int s = __ldg(&src[e]);
    int d = __ldg(&dst[e]);
    float4 m = reinterpret_cast<const float4*>(g_w)[s * 8 + q];
    atomicAdd(&reinterpret_cast<float4*>(g_acc)[d * 8 + q], m);
}

// ---------------------------------------------------------------------------
// K4: out[b][z] = dinv_z*(acc[z][b] + w[z][b]) + const, float4 everywhere,
// 32x32 tile transpose, 256 threads/block. Self-cleans acc and deg.
// ---------------------------------------------------------------------------
__global__ void k_out(float* __restrict__ out) {
    __shared__ float tile[32][33];
    const int tx = threadIdx.x;
    const int zb = blockIdx.x * 32;           // NZ % 32 == 0 (4000 = 125*32)

    // read side: thread (zi = tx>>3, q = tx&7) handles float4 q of row zb+zi
    int zi = tx >> 3;
    int q  = tx & 7;
    int z  = zb + zi;
    int ridx = z * 8 + q;                     // float4 index into acc/w rows
    float dinv = rsqrtf((float)(g_deg[z] + 1));   // broadcast among 8 threads
    float4 a4 = reinterpret_cast<const float4*>(g_acc)[ridx];
    float4 w4 = reinterpret_cast<const float4*>(g_w)[ridx];
    tile[zi][q * 4 + 0] = dinv * (a4.x + w4.x);
    tile[zi][q * 4 + 1] = dinv * (a4.y + w4.y);
    tile[zi][q * 4 + 2] = dinv * (a4.z + w4.z);
    tile[zi][q * 4 + 3] = dinv * (a4.w + w4.w);
    __syncthreads();

    // self-clean (all reads of acc/deg happened before the sync)
    reinterpret_cast<float4*>(g_acc)[ridx] = make_float4(0.f, 0.f, 0.f, 0.f);
    if (tx < 32) g_deg[zb + tx] = 0;

    // write side: thread (b = tx>>3, zq = tx&7) writes out[b][zb+4zq .. +3]
    int b  = tx >> 3;
    int zq = tx & 7;
    float c = g_const;
    float4 o;
    o.x = tile[zq * 4 + 0][b] + c;
    o.y = tile[zq * 4 + 1][b] + c;
    o.z = tile[zq * 4 + 2][b] + c;
    o.w = tile[zq * 4 + 3][b] + c;
    reinterpret_cast<float4*>(out)[((size_t)b * NZ + zb) / 4 + zq] = o;
}

// ---------------------------------------------------------------------------
extern "C" void kernel_launch(void* const* d_in, const int* in_sizes, int n_in,
                              void* d_out, int out_size) {
    const float* x    = (const float*)d_in[0];   // [32,4000,32]
    const int*   ei   = (const int*)  d_in[1];   // [2,64000]
    const float* W    = (const float*)d_in[2];   // [32,64]
    const float* bias = (const float*)d_in[3];   // [64]
    const float* fcW  = (const float*)d_in[4];   // [64]
    const float* fcb  = (const float*)d_in[5];   // [1]
    float* out = (float*)d_out;                  // [32,4000]

    const int* src = ei;
    const int* dst = ei + NE;

    k_hist_v<<<NEB + 1, 256>>>(dst, W, bias, fcW, fcb);
    k_ydot<<<NYB, 256>>>(x);
    k_scatter<<<(NE * 8) / 256, 256>>>(src, dst);
    k_out<<<NZ / 32, 256>>>(out);
}